// round 8
// baseline (speedup 1.0000x reference)
#include <cuda_runtime.h>

// Problem constants (from reference setup_inputs)
#define B 8
#define H 100
#define W 100
#define C 512
#define R 300
#define POOL 7

// grid: (R, POOL, B). One block per (roi, py) row of 7 px cells for one batch.
// 128 threads; thread t covers channels {2t, 2t+1, 2t+256, 2t+257} via LDG.64 /
// STG.64 (B300 L1tex services cross-LDG wavefronts at ~1.0 cyc vs 2.07 for
// within-LDG replays, making 64-bit accesses cheaper per byte than 128-bit
// when L1tex-replay-bound).
__global__ __launch_bounds__(128, 12) void roi_align_kernel(
    const float* __restrict__ x,     // (B, H, W, C)
    const int*   __restrict__ rois,  // (R, 4): x1, y1, w, h
    float*       __restrict__ out)   // (B, R, 7, 7, C)
{
    const int r  = blockIdx.x;
    const int py = blockIdx.y;
    const int b  = blockIdx.z;

    const int4 roi = __ldg(((const int4*)rois) + r);
    const int x1 = roi.x, y1 = roi.y, w = roi.z, h = roi.w;

    // --- y axis coords, once per block (replicates JAX fp32 math) ---
    const float sh = (float)h;
    float vy = fmaf((float)py + 0.5f, sh * (1.0f / POOL), -0.5f);
    vy = fminf(fmaxf(vy, 0.0f), sh - 1.0f);
    const float fly = floorf(vy);
    const int   ylo = (int)fly;
    const float fy  = vy - fly;
    const int   yhi = min(ylo + 1, h - 1);

    // x-axis common subexpressions
    const float sw   = (float)w;
    const float stpx = sw * (1.0f / POOL);
    const float clx  = sw - 1.0f;
    const int   xmax = w - 1;

    const int c0 = threadIdx.x * 2;        // channels c0, c0+1
    const int c1 = c0 + 256;               // channels c1, c1+1

    // 32-bit element offsets (max < 2^31)
    const unsigned rowl_off = (unsigned)(b * (H * W) + (y1 + ylo) * W) * C;
    const unsigned rowh_off = (unsigned)(b * (H * W) + (y1 + yhi) * W) * C;
    const unsigned out_base = (unsigned)((b * R + r) * 49 + py * POOL) * C;

    const float gy = 1.0f - fy;

    #pragma unroll
    for (int px = 0; px < POOL; ++px) {
        // --- x axis coords for this cell (px is a literal) ---
        float vx = fmaf((float)px + 0.5f, stpx, -0.5f);
        vx = fminf(fmaxf(vx, 0.0f), clx);
        float flx = floorf(vx);
        int   xlo = (int)flx;
        float fx  = vx - flx;
        int   xhi = min(xlo + 1, xmax);

        const unsigned ol = (unsigned)(x1 + xlo) * C;
        const unsigned oh = (unsigned)(x1 + xhi) * C;

        // 8 independent LDG.64, all warp-coalesced (256B contiguous per warp)
        float2 tl0 = *(const float2*)(x + rowl_off + ol + c0);
        float2 tl1 = *(const float2*)(x + rowl_off + ol + c1);
        float2 tr0 = *(const float2*)(x + rowl_off + oh + c0);
        float2 tr1 = *(const float2*)(x + rowl_off + oh + c1);
        float2 bl0 = *(const float2*)(x + rowh_off + ol + c0);
        float2 bl1 = *(const float2*)(x + rowh_off + ol + c1);
        float2 br0 = *(const float2*)(x + rowh_off + oh + c0);
        float2 br1 = *(const float2*)(x + rowh_off + oh + c1);

        // bilinear weights
        const float gx = 1.0f - fx;
        const float w_tl = gx * gy;
        const float w_tr = fx * gy;
        const float w_bl = gx * fy;
        const float w_br = fx * fy;

        float2 o0, o1;
        o0.x = fmaf(br0.x, w_br, fmaf(bl0.x, w_bl, fmaf(tr0.x, w_tr, tl0.x * w_tl)));
        o0.y = fmaf(br0.y, w_br, fmaf(bl0.y, w_bl, fmaf(tr0.y, w_tr, tl0.y * w_tl)));
        o1.x = fmaf(br1.x, w_br, fmaf(bl1.x, w_bl, fmaf(tr1.x, w_tr, tl1.x * w_tl)));
        o1.y = fmaf(br1.y, w_br, fmaf(bl1.y, w_bl, fmaf(tr1.y, w_tr, tl1.y * w_tl)));

        // output is never re-read: streaming 64-bit stores
        float* po = out + out_base + (unsigned)px * C;
        __stcs((float2*)(po + c0), o0);
        __stcs((float2*)(po + c1), o1);
    }
}

extern "C" void kernel_launch(void* const* d_in, const int* in_sizes, int n_in,
                              void* d_out, int out_size)
{
    const float* x    = (const float*)d_in[0];
    const int*   rois = (const int*)d_in[1];
    float*       out  = (float*)d_out;

    dim3 grid(R, POOL, B);   // 16,800 blocks; z-slowest => per-batch L2 locality
    roi_align_kernel<<<grid, 128>>>(x, rois, out);
}

// round 9
// speedup vs baseline: 1.0496x; 1.0496x over previous
#include <cuda_runtime.h>

// Problem constants (from reference setup_inputs)
#define B 8
#define H 100
#define W 100
#define C 512
#define R 300
#define POOL 7

// grid: (R, POOL, B). One block per (roi, py) row of 7 px cells for one batch.
// 128 threads * float4 = 512 channels (LDG.128 throughout — R8 falsified the
// 64-bit-load theory). Corner dedup: when xlo(px+1)==xhi(px) (all ROIs with
// w<=13), reuse the previous cell's tr/br registers as this cell's tl/bl,
// skipping 2 of 4 loads. Check is block-uniform (same ROI) -> no divergence.
__global__ __launch_bounds__(128, 12) void roi_align_kernel(
    const float* __restrict__ x,     // (B, H, W, C)
    const int*   __restrict__ rois,  // (R, 4): x1, y1, w, h
    float*       __restrict__ out)   // (B, R, 7, 7, C)
{
    const int r  = blockIdx.x;
    const int py = blockIdx.y;
    const int b  = blockIdx.z;

    const int4 roi = __ldg(((const int4*)rois) + r);
    const int x1 = roi.x, y1 = roi.y, w = roi.z, h = roi.w;

    // --- y axis coords, once per block (replicates JAX fp32 math) ---
    const float sh = (float)h;
    float vy = fmaf((float)py + 0.5f, sh * (1.0f / POOL), -0.5f);
    vy = fminf(fmaxf(vy, 0.0f), sh - 1.0f);
    const float fly = floorf(vy);
    const int   ylo = (int)fly;
    const float fy  = vy - fly;
    const int   yhi = min(ylo + 1, h - 1);

    // x-axis common subexpressions
    const float sw   = (float)w;
    const float stpx = sw * (1.0f / POOL);
    const float clx  = sw - 1.0f;
    const int   xmax = w - 1;

    const int c = threadIdx.x * 4;

    // 32-bit element offsets (max < 2^31)
    const unsigned rowl_off = (unsigned)(b * (H * W) + (y1 + ylo) * W) * C + c;
    const unsigned rowh_off = (unsigned)(b * (H * W) + (y1 + yhi) * W) * C + c;
    const unsigned out_base = (unsigned)((b * R + r) * 49 + py * POOL) * C + c;

    const float gy = 1.0f - fy;

    // carried right-edge state for dedup
    float4  ptr_c, pbr_c;             // previous cell's tr / br
    unsigned prev_oh = 0xFFFFFFFFu;   // previous cell's right-column offset

    #pragma unroll
    for (int px = 0; px < POOL; ++px) {
        // --- x axis coords for this cell (px is a literal) ---
        float vx = fmaf((float)px + 0.5f, stpx, -0.5f);
        vx = fminf(fmaxf(vx, 0.0f), clx);
        float flx = floorf(vx);
        int   xlo = (int)flx;
        float fx  = vx - flx;
        int   xhi = min(xlo + 1, xmax);

        const unsigned ol = (unsigned)(x1 + xlo) * C;
        const unsigned oh = (unsigned)(x1 + xhi) * C;

        // left corners: reuse previous right corners when columns coincide
        float4 tl, bl;
        if (ol == prev_oh) {          // block-uniform condition
            tl = ptr_c;
            bl = pbr_c;
        } else {
            tl = *(const float4*)(x + rowl_off + ol);
            bl = *(const float4*)(x + rowh_off + ol);
        }

        // right corners: always loaded
        float4 tr = *(const float4*)(x + rowl_off + oh);
        float4 br = *(const float4*)(x + rowh_off + oh);

        // bilinear weights
        const float gx = 1.0f - fx;
        const float w_tl = gx * gy;
        const float w_tr = fx * gy;
        const float w_bl = gx * fy;
        const float w_br = fx * fy;

        float4 o;
        o.x = fmaf(br.x, w_br, fmaf(bl.x, w_bl, fmaf(tr.x, w_tr, tl.x * w_tl)));
        o.y = fmaf(br.y, w_br, fmaf(bl.y, w_bl, fmaf(tr.y, w_tr, tl.y * w_tl)));
        o.z = fmaf(br.z, w_br, fmaf(bl.z, w_bl, fmaf(tr.z, w_tr, tl.z * w_tl)));
        o.w = fmaf(br.w, w_br, fmaf(bl.w, w_bl, fmaf(tr.w, w_tr, tl.w * w_tl)));

        // output is never re-read: streaming store
        __stcs((float4*)(out + out_base + (unsigned)px * C), o);

        // roll right edge into carried state
        prev_oh = oh;
        ptr_c = tr;
        pbr_c = br;
    }
}

extern "C" void kernel_launch(void* const* d_in, const int* in_sizes, int n_in,
                              void* d_out, int out_size)
{
    const float* x    = (const float*)d_in[0];
    const int*   rois = (const int*)d_in[1];
    float*       out  = (float*)d_out;

    dim3 grid(R, POOL, B);   // 16,800 blocks; z-slowest => per-batch L2 locality
    roi_align_kernel<<<grid, 128>>>(x, rois, out);
}

// round 10
// speedup vs baseline: 1.1216x; 1.0685x over previous
#include <cuda_runtime.h>
#include <cstdint>

// Problem constants (from reference setup_inputs)
#define B 8
#define H 100
#define W 100
#define C 512
#define R 300
#define POOL 7
#define ROWBYTES (C * sizeof(float))   // 2048 bytes per channel row

// ---- PTX helpers ----
__device__ __forceinline__ uint32_t smem_u32(const void* p) {
    uint32_t a;
    asm("{ .reg .u64 t; cvta.to.shared.u64 t, %1; cvt.u32.u64 %0, t; }"
        : "=r"(a) : "l"(p));
    return a;
}
__device__ __forceinline__ void mbar_init(uint32_t mbar, uint32_t count) {
    asm volatile("mbarrier.init.shared.b64 [%0], %1;" :: "r"(mbar), "r"(count) : "memory");
}
__device__ __forceinline__ void mbar_expect_tx(uint32_t mbar, uint32_t bytes) {
    asm volatile("mbarrier.arrive.expect_tx.shared.b64 _, [%0], %1;"
                 :: "r"(mbar), "r"(bytes) : "memory");
}
__device__ __forceinline__ void mbar_wait(uint32_t mbar, uint32_t parity) {
    asm volatile(
        "{\n\t.reg .pred P;\n\t"
        "LW%=:\n\t"
        "mbarrier.try_wait.parity.acquire.cta.shared::cta.b64 P, [%0], %1, 0x989680;\n\t"
        "@!P bra LW%=;\n\t}"
        :: "r"(mbar), "r"(parity) : "memory");
}
__device__ __forceinline__ void bulk_g2s(uint32_t dst, const void* src,
                                         uint32_t bytes, uint32_t mbar) {
    asm volatile(
        "cp.async.bulk.shared::cluster.global.mbarrier::complete_tx::bytes "
        "[%0], [%1], %2, [%3];"
        :: "r"(dst), "l"(src), "r"(bytes), "r"(mbar) : "memory");
}
__device__ __forceinline__ void fence_proxy_async_cta() {
    asm volatile("fence.proxy.async.shared::cta;" ::: "memory");
}

struct __align__(128) Stage {
    float tl[C], tr[C], bl[C], br[C];   // 8 KB
};

// grid: (R, POOL, B). One block per (roi, py) row; 7 px cells.
// Corner rows (2KB each) are staged into smem by 1-D TMA bulk copies
// (double-buffered, 2 cells ahead); compute reads smem via LDS.128.
__global__ __launch_bounds__(128) void roi_align_tma_kernel(
    const float* __restrict__ x,     // (B, H, W, C)
    const int*   __restrict__ rois,  // (R, 4): x1, y1, w, h
    float*       __restrict__ out)   // (B, R, 7, 7, C)
{
    __shared__ Stage s_buf[2];
    __shared__ unsigned long long s_mbar[2];

    const int r  = blockIdx.x;
    const int py = blockIdx.y;
    const int b  = blockIdx.z;
    const int tid = threadIdx.x;

    const int4 roi = __ldg(((const int4*)rois) + r);
    const int x1 = roi.x, y1 = roi.y, w = roi.z, h = roi.w;

    // --- y axis coords, once per block (replicates JAX fp32 math) ---
    const float sh = (float)h;
    float vy = fmaf((float)py + 0.5f, sh * (1.0f / POOL), -0.5f);
    vy = fminf(fmaxf(vy, 0.0f), sh - 1.0f);
    const float fly = floorf(vy);
    const int   ylo = (int)fly;
    const float fy  = vy - fly;
    const int   yhi = min(ylo + 1, h - 1);

    // x-axis common subexpressions
    const float sw   = (float)w;
    const float stpx = sw * (1.0f / POOL);
    const float clx  = sw - 1.0f;
    const int   xmax = w - 1;

    const unsigned rowl_off = (unsigned)(b * (H * W) + (y1 + ylo) * W) * C;
    const unsigned rowh_off = (unsigned)(b * (H * W) + (y1 + yhi) * W) * C;
    const unsigned out_base = (unsigned)((b * R + r) * 49 + py * POOL) * C;

    const uint32_t mb[2] = { smem_u32(&s_mbar[0]), smem_u32(&s_mbar[1]) };
    const uint32_t bufa[2] = { smem_u32(&s_buf[0]), smem_u32(&s_buf[1]) };

    // Producer staging: compute x-coords for cell px, issue 4 bulk copies.
    auto stage = [&](int px, int st) {
        float vx = fmaf((float)px + 0.5f, stpx, -0.5f);
        vx = fminf(fmaxf(vx, 0.0f), clx);
        int xlo = (int)floorf(vx);
        int xhi = min(xlo + 1, xmax);
        const unsigned ol = (unsigned)(x1 + xlo) * C;
        const unsigned oh = (unsigned)(x1 + xhi) * C;
        mbar_expect_tx(mb[st], 4 * (uint32_t)ROWBYTES);
        bulk_g2s(bufa[st] + 0 * ROWBYTES, x + rowl_off + ol, ROWBYTES, mb[st]); // tl
        bulk_g2s(bufa[st] + 1 * ROWBYTES, x + rowl_off + oh, ROWBYTES, mb[st]); // tr
        bulk_g2s(bufa[st] + 2 * ROWBYTES, x + rowh_off + ol, ROWBYTES, mb[st]); // bl
        bulk_g2s(bufa[st] + 3 * ROWBYTES, x + rowh_off + oh, ROWBYTES, mb[st]); // br
    };

    if (tid == 0) {
        mbar_init(mb[0], 1);
        mbar_init(mb[1], 1);
        fence_proxy_async_cta();
        stage(0, 0);
        stage(1, 1);
    }
    __syncthreads();

    const int c = tid * 4;
    const float gy = 1.0f - fy;

    #pragma unroll
    for (int px = 0; px < POOL; ++px) {
        const int st = px & 1;
        const int ph = (px >> 1) & 1;

        // x fractional weight for this cell (all threads, cheap)
        float vx = fmaf((float)px + 0.5f, stpx, -0.5f);
        vx = fminf(fmaxf(vx, 0.0f), clx);
        const float fx = vx - floorf(vx);

        mbar_wait(mb[st], ph);

        const float4 tl = *(const float4*)(&s_buf[st].tl[c]);
        const float4 tr = *(const float4*)(&s_buf[st].tr[c]);
        const float4 bl = *(const float4*)(&s_buf[st].bl[c]);
        const float4 br = *(const float4*)(&s_buf[st].br[c]);

        const float gx = 1.0f - fx;
        const float w_tl = gx * gy;
        const float w_tr = fx * gy;
        const float w_bl = gx * fy;
        const float w_br = fx * fy;

        float4 o;
        o.x = fmaf(br.x, w_br, fmaf(bl.x, w_bl, fmaf(tr.x, w_tr, tl.x * w_tl)));
        o.y = fmaf(br.y, w_br, fmaf(bl.y, w_bl, fmaf(tr.y, w_tr, tl.y * w_tl)));
        o.z = fmaf(br.z, w_br, fmaf(bl.z, w_bl, fmaf(tr.z, w_tr, tl.z * w_tl)));
        o.w = fmaf(br.w, w_br, fmaf(bl.w, w_bl, fmaf(tr.w, w_tr, tl.w * w_tl)));

        __stcs((float4*)(out + out_base + (unsigned)px * C + c), o);

        __syncthreads();                    // all warps done reading buf[st]
        if (tid == 0 && px + 2 < POOL) {
            stage(px + 2, st);              // reuse freed buffer
        }
    }
}

extern "C" void kernel_launch(void* const* d_in, const int* in_sizes, int n_in,
                              void* d_out, int out_size)
{
    const float* x    = (const float*)d_in[0];
    const int*   rois = (const int*)d_in[1];
    float*       out  = (float*)d_out;

    dim3 grid(R, POOL, B);   // 16,800 blocks; z-slowest => per-batch L2 locality
    roi_align_tma_kernel<<<grid, 128>>>(x, rois, out);
}

// round 13
// speedup vs baseline: 1.1283x; 1.0060x over previous
#include <cuda_runtime.h>
#include <cstdint>

// Problem constants (from reference setup_inputs)
#define B 8
#define H 100
#define W 100
#define C 512
#define R 300
#define POOL 7
#define ROWBYTES 2048u                 // C * sizeof(float)
#define STAGES 3

// ---- PTX helpers ----
__device__ __forceinline__ uint32_t smem_u32(const void* p) {
    uint32_t a;
    asm("{ .reg .u64 t; cvta.to.shared.u64 t, %1; cvt.u32.u64 %0, t; }"
        : "=r"(a) : "l"(p));
    return a;
}
__device__ __forceinline__ void mbar_init(uint32_t mbar, uint32_t count) {
    asm volatile("mbarrier.init.shared.b64 [%0], %1;" :: "r"(mbar), "r"(count) : "memory");
}
__device__ __forceinline__ void mbar_expect_tx(uint32_t mbar, uint32_t bytes) {
    asm volatile("mbarrier.arrive.expect_tx.shared.b64 _, [%0], %1;"
                 :: "r"(mbar), "r"(bytes) : "memory");
}
__device__ __forceinline__ void mbar_arrive(uint32_t mbar) {
    asm volatile("mbarrier.arrive.shared.b64 _, [%0];" :: "r"(mbar) : "memory");
}
__device__ __forceinline__ void mbar_wait(uint32_t mbar, uint32_t parity) {
    asm volatile(
        "{\n\t.reg .pred P;\n\t"
        "LW%=:\n\t"
        "mbarrier.try_wait.parity.acquire.cta.shared::cta.b64 P, [%0], %1, 0x989680;\n\t"
        "@!P bra LW%=;\n\t}"
        :: "r"(mbar), "r"(parity) : "memory");
}
__device__ __forceinline__ void bulk_g2s(uint32_t dst, const void* src,
                                         uint32_t bytes, uint32_t mbar) {
    asm volatile(
        "cp.async.bulk.shared::cluster.global.mbarrier::complete_tx::bytes "
        "[%0], [%1], %2, [%3];"
        :: "r"(dst), "l"(src), "r"(bytes), "r"(mbar) : "memory");
}
__device__ __forceinline__ void fence_proxy_async_cta() {
    asm volatile("fence.proxy.async.shared::cta;" ::: "memory");
}

struct __align__(128) Stage {
    float tl[C], tr[C], bl[C], br[C];   // tl|tr and bl|br are contiguous 4KB
};

// grid: (R, POOL, B). One block per (roi, py) row; 7 px cells.
// 3-stage TMA ring with full/empty mbarriers (no __syncthreads in the loop).
// Each cell stages 8KB via two 4KB bulk copies (adjacent x-columns contiguous).
__global__ __launch_bounds__(128) void roi_align_tma_kernel(
    const float* __restrict__ x,     // (B, H, W, C)
    const int*   __restrict__ rois,  // (R, 4): x1, y1, w, h
    float*       __restrict__ out)   // (B, R, 7, 7, C)
{
    __shared__ Stage s_buf[STAGES];
    __shared__ unsigned long long s_full[STAGES], s_empty[STAGES];

    const int r  = blockIdx.x;
    const int py = blockIdx.y;
    const int b  = blockIdx.z;
    const int tid = threadIdx.x;

    const int4 roi = __ldg(((const int4*)rois) + r);
    const int x1 = roi.x, y1 = roi.y, w = roi.z, h = roi.w;

    // --- y axis coords, once per block (replicates JAX fp32 math) ---
    const float sh = (float)h;
    float vy = fmaf((float)py + 0.5f, sh * (1.0f / POOL), -0.5f);
    vy = fminf(fmaxf(vy, 0.0f), sh - 1.0f);
    const float fly = floorf(vy);
    const int   ylo = (int)fly;
    const float fy  = vy - fly;
    const int   yhi = min(ylo + 1, h - 1);

    // x-axis common subexpressions
    const float sw   = (float)w;
    const float stpx = sw * (1.0f / POOL);
    const float clx  = sw - 1.0f;
    const int   xmax = w - 1;

    const unsigned rowl_off = (unsigned)(b * (H * W) + (y1 + ylo) * W) * C;
    const unsigned rowh_off = (unsigned)(b * (H * W) + (y1 + yhi) * W) * C;
    const unsigned out_base = (unsigned)((b * R + r) * 49 + py * POOL) * C;

    uint32_t fullb[STAGES], emptyb[STAGES], bufa[STAGES];
    #pragma unroll
    for (int s = 0; s < STAGES; ++s) {
        fullb[s]  = smem_u32(&s_full[s]);
        emptyb[s] = smem_u32(&s_empty[s]);
        bufa[s]   = smem_u32(&s_buf[s]);
    }

    // Producer staging for cell px into stage st (issued by thread 0 only).
    auto stage = [&](int px, int st) {
        float vx = fmaf((float)px + 0.5f, stpx, -0.5f);
        vx = fminf(fmaxf(vx, 0.0f), clx);
        int xlo = (int)floorf(vx);
        int xhi = min(xlo + 1, xmax);
        const unsigned ol = (unsigned)(x1 + xlo) * C;
        mbar_expect_tx(fullb[st], 2 * 4096u);
        if (xhi == xlo + 1) {
            // adjacent columns are contiguous: one 4KB copy covers tl|tr (and bl|br)
            bulk_g2s(bufa[st],                x + rowl_off + ol, 4096u, fullb[st]);
            bulk_g2s(bufa[st] + 2 * ROWBYTES, x + rowh_off + ol, 4096u, fullb[st]);
        } else {
            // clamped: xhi == xlo, duplicate the single column into both slots
            const unsigned oh = (unsigned)(x1 + xhi) * C;
            bulk_g2s(bufa[st],                x + rowl_off + ol, ROWBYTES, fullb[st]);
            bulk_g2s(bufa[st] + ROWBYTES,     x + rowl_off + oh, ROWBYTES, fullb[st]);
            bulk_g2s(bufa[st] + 2 * ROWBYTES, x + rowh_off + ol, ROWBYTES, fullb[st]);
            bulk_g2s(bufa[st] + 3 * ROWBYTES, x + rowh_off + oh, ROWBYTES, fullb[st]);
        }
    };

    if (tid == 0) {
        #pragma unroll
        for (int s = 0; s < STAGES; ++s) {
            mbar_init(fullb[s], 1);       // completed by expect_tx drain
            mbar_init(emptyb[s], 128);    // all threads arrive after reading
        }
        fence_proxy_async_cta();
    }
    __syncthreads();

    if (tid == 0) {
        stage(0, 0);
        stage(1, 1);
        stage(2, 2);
    }

    const int c = tid * 4;
    const float gy = 1.0f - fy;

    #pragma unroll
    for (int px = 0; px < POOL; ++px) {
        const int st        = px % STAGES;
        const int use       = px / STAGES;
        const uint32_t upar = (uint32_t)(use & 1);

        // x fractional weight for this cell
        float vx = fmaf((float)px + 0.5f, stpx, -0.5f);
        vx = fminf(fmaxf(vx, 0.0f), clx);
        const float fx = vx - floorf(vx);

        mbar_wait(fullb[st], upar);

        const float4 tl = *(const float4*)(&s_buf[st].tl[c]);
        const float4 tr = *(const float4*)(&s_buf[st].tr[c]);
        const float4 bl = *(const float4*)(&s_buf[st].bl[c]);
        const float4 br = *(const float4*)(&s_buf[st].br[c]);

        const float gx = 1.0f - fx;
        const float w_tl = gx * gy;
        const float w_tr = fx * gy;
        const float w_bl = gx * fy;
        const float w_br = fx * fy;

        float4 o;
        o.x = fmaf(br.x, w_br, fmaf(bl.x, w_bl, fmaf(tr.x, w_tr, tl.x * w_tl)));
        o.y = fmaf(br.y, w_br, fmaf(bl.y, w_bl, fmaf(tr.y, w_tr, tl.y * w_tl)));
        o.z = fmaf(br.z, w_br, fmaf(bl.z, w_bl, fmaf(tr.z, w_tr, tl.z * w_tl)));
        o.w = fmaf(br.w, w_br, fmaf(bl.w, w_bl, fmaf(tr.w, w_tr, tl.w * w_tl)));

        __stcs((float4*)(out + out_base + (unsigned)px * C + c), o);

        // signal this stage's buffer is free (data already consumed into regs)
        mbar_arrive(emptyb[st]);

        // producer refills the ring after this use's 128 arrives complete.
        // The use-th completion of the empty barrier is phase `use` -> parity use&1.
        if (tid == 0 && px + STAGES < POOL) {
            mbar_wait(emptyb[st], upar);
            stage(px + STAGES, st);
        }
    }
}

extern "C" void kernel_launch(void* const* d_in, const int* in_sizes, int n_in,
                              void* d_out, int out_size)
{
    const float* x    = (const float*)d_in[0];
    const int*   rois = (const int*)d_in[1];
    float*       out  = (float*)d_out;

    dim3 grid(R, POOL, B);   // 16,800 blocks; z-slowest => per-batch L2 locality
    roi_align_tma_kernel<<<grid, 128>>>(x, rois, out);
}